// round 9
// baseline (speedup 1.0000x reference)
#include <cuda_runtime.h>

// SSIM loss: depthwise 11x11 gaussian (separable) + pointwise SSIM + global mean.
// B=16, C=3, H=W=512. Planes = 48. Tile 32x32 per block, halo 5 each side.
//
// Round 9: fused-pair phase 2. Each P2 task reads its 18-value row window ONCE,
// forms (t^2+i^2, t*i) once, and accumulates BOTH blur pairs (8 cols each,
// 4 chunks x 42 rows = 168 tasks). Kills the 2x redundant row re-read that made
// P2 loads the largest L1 line item. P3 keeps the reg-lean pair-split + smem
// exchange from round 8. occ 6, FFMA2 throughout.

typedef unsigned long long u64;

#define TW 32
#define TH 32
#define HALO 5
#define SH 42
#define SW 42
#define IMG 512
#define NPLANES 48

#define RS 90            // (t,i) pair-plane row stride (floats): 26*l mod 64 period 32 -> LDS.64 conflict-free
#define PP 3780          // SH * RS
#define CS 84            // sHT column stride (floats): quad 5*tx mod 8 distinct -> LDS.128 conflict-free
#define PT 2688          // 32 * CS, per-pair sHT plane

#define OFF_HT PP
#define OFF_RED (OFF_HT + 2 * PT)
#define SMEM_FLOATS (OFF_RED + 8)
#define SMEM_BYTES (SMEM_FLOATS * 4)   // 36656 B -> 6 blocks/SM

__device__ constexpr float GW[11] = {
    0.00102838f, 0.00759877f, 0.03600077f, 0.10936079f, 0.21300554f,
    0.26601173f,
    0.21300554f, 0.10936079f, 0.03600077f, 0.00759877f, 0.00102838f};

#define SSIM_C1 0.0001f
#define SSIM_C2 0.0009f
#define INV_N (1.0f / (16.0f * 3.0f * 512.0f * 512.0f))

__device__ __forceinline__ u64 pack2(float lo, float hi) {
    u64 r;
    asm("mov.b64 %0, {%1, %2};" : "=l"(r) : "f"(lo), "f"(hi));
    return r;
}
__device__ __forceinline__ void unpack2(u64 v, float& lo, float& hi) {
    asm("mov.b64 {%0, %1}, %2;" : "=f"(lo), "=f"(hi) : "l"(v));
}
__device__ __forceinline__ u64 ffma2(u64 a, u64 b, u64 c) {
    u64 d;
    asm("fma.rn.f32x2 %0, %1, %2, %3;" : "=l"(d) : "l"(a), "l"(b), "l"(c));
    return d;
}
__device__ __forceinline__ u64 bcast2(float g) {
    unsigned u = __float_as_uint(g);
    return ((u64)u << 32) | (u64)u;
}

// Streaming vertical blur: 8 outputs from 18 consecutive row values of one column.
__device__ __forceinline__ void v_blur8(const float* __restrict__ base, u64 (&acc)[8]) {
#pragma unroll
    for (int r = 0; r < 8; r++) acc[r] = 0ull;
#pragma unroll
    for (int q = 0; q < 9; q++) {
        ulonglong2 vv = *(const ulonglong2*)(base + q * 4);
#pragma unroll
        for (int e = 0; e < 2; e++) {
            const int j = 2 * q + e;
            u64 v = e ? vv.y : vv.x;
#pragma unroll
            for (int r = 0; r < 8; r++) {
                if (j - r >= 0 && j - r < 11) acc[r] = ffma2(v, bcast2(GW[j - r]), acc[r]);
            }
        }
    }
}

__global__ void zero_out_kernel(float* out) { out[0] = 0.0f; }

__global__ __launch_bounds__(256, 6)
void ssim_kernel(const float* __restrict__ input, const float* __restrict__ target,
                 float* __restrict__ out) {
    extern __shared__ float smem[];
    float* sHT = smem + OFF_HT;
    float* red = smem + OFF_RED;

    const int tid = threadIdx.x;
    const int plane = blockIdx.z;
    const float* Tp = target + (size_t)plane * (IMG * IMG);
    const float* Ip = input + (size_t)plane * (IMG * IMG);
    const int gx0 = blockIdx.x * TW - HALO;
    const int gy0 = blockIdx.y * TH - HALO;

    // ---- Phase 1: load tile (+halo), store interleaved (t,i) pairs ----
    for (int idx = tid; idx < SH * SW; idx += 256) {
        int r = idx / SW;
        int c = idx - r * SW;
        int gx = gx0 + c;
        int gy = gy0 + r;
        float t = 0.0f, v = 0.0f;
        if ((unsigned)gx < (unsigned)IMG && (unsigned)gy < (unsigned)IMG) {
            t = Tp[gy * IMG + gx];
            v = Ip[gy * IMG + gx];
        }
        *(u64*)(smem + r * RS + c * 2) = pack2(t, v);
    }
    __syncthreads();

    // ---- Phase 2: fused-pair horizontal blur.
    // Task = (row, 8-col chunk). Warps 0-3: chunk = w, row = lane (0..31).
    // Warps 4-7: idx = (w-4)*32+lane < 40 -> chunk = idx/10, row = 32 + idx%10.
    {
        const int w = tid >> 5;
        const int lane = tid & 31;
        int row, c0;
        bool active = true;
        if (w < 4) {
            c0 = w * 8;
            row = lane;
        } else {
            int idx = (w - 4) * 32 + lane;
            active = (idx < 40);
            int chunk = idx / 10;
            row = 32 + idx - chunk * 10;
            c0 = chunk * 8;
        }
        if (active) {
            const float* rowBase = smem + row * RS + c0 * 2;
            u64 a0[8], a1[8];
#pragma unroll
            for (int r = 0; r < 8; r++) { a0[r] = 0ull; a1[r] = 0ull; }
#pragma unroll
            for (int j = 0; j < 18; j++) {
                u64 v = *(const u64*)(rowBase + j * 2);
                float t, i;
                unpack2(v, t, i);
                u64 p = pack2(fmaf(t, t, i * i), t * i);
#pragma unroll
                for (int r = 0; r < 8; r++) {
                    if (j - r >= 0 && j - r < 11) {
                        a0[r] = ffma2(v, bcast2(GW[j - r]), a0[r]);
                        a1[r] = ffma2(p, bcast2(GW[j - r]), a1[r]);
                    }
                }
            }
            float* d0 = sHT + c0 * CS + row * 2;
            float* d1 = d0 + PT;
#pragma unroll
            for (int r = 0; r < 8; r++) {
                *(u64*)(d0 + r * CS) = a0[r];
                *(u64*)(d1 + r * CS) = a1[r];
            }
        }
    }
    __syncthreads();

    // ---- Phase 3: all-warp vertical blur (round-8 structure).
    const int pair = tid >> 7;        // warps 0-3 -> pair 0, warps 4-7 -> pair 1
    const int tx = tid & 31;
    const int tg = (tid >> 5) & 3;    // output rows [8*tg, 8*tg+8)

    u64 res[8];
    v_blur8(sHT + pair * PT + tx * CS + tg * 16, res);
    __syncthreads();  // all sHT reads complete before pair-1 plane is reused

    // pair-1 threads publish into scratch in the (dead) pair-1 plane.
    // slot stride 20 floats: 16B aligned, quad 5*tx mod 8 distinct -> conflict-free.
    if (pair == 1) {
        float* x = sHT + PT + (tx + tg * 32) * 20;
#pragma unroll
        for (int q = 0; q < 4; q++) {
            ulonglong2 vv;
            vv.x = res[2 * q];
            vv.y = res[2 * q + 1];
            *(ulonglong2*)(x + q * 4) = vv;
        }
    }
    __syncthreads();

    if (pair == 0) {
        u64 pr[8];
        const float* x = sHT + PT + (tx + tg * 32) * 20;
#pragma unroll
        for (int q = 0; q < 4; q++) {
            ulonglong2 vv = *(const ulonglong2*)(x + q * 4);
            pr[2 * q] = vv.x;
            pr[2 * q + 1] = vv.y;
        }

        float acc = 0.0f;
#pragma unroll
        for (int r = 0; r < 8; r++) {
            float mu1, mu2, eq, e12;
            unpack2(res[r], mu1, mu2);
            unpack2(pr[r], eq, e12);
            float mu1s = mu1 * mu1;
            float mu2s = mu2 * mu2;
            float mu12 = mu1 * mu2;
            float musum = mu1s + mu2s;
            float ssum = eq - musum;   // sigma1^2 + sigma2^2
            float s12 = e12 - mu12;
            float num = (2.0f * mu12 + SSIM_C1) * (2.0f * s12 + SSIM_C2);
            float den = (musum + SSIM_C1) * (ssum + SSIM_C2);
            float ssim = __fdividef(num, den);
            u64 tv = *(const u64*)(smem + (HALO + tg * 8 + r) * RS + (HALO + tx) * 2);
            float tc, ic;
            unpack2(tv, tc, ic);
            acc += (tc > 0.0f) ? (1.0f - ssim) : 0.0f;
        }

#pragma unroll
        for (int off = 16; off; off >>= 1) acc += __shfl_xor_sync(0xFFFFFFFFu, acc, off);
        if (tx == 0) red[tg] = acc;
    }
    __syncthreads();
    if (tid == 0) {
        float s = red[0] + red[1] + red[2] + red[3];
        atomicAdd(out, s * INV_N);
    }
}

extern "C" void kernel_launch(void* const* d_in, const int* in_sizes, int n_in,
                              void* d_out, int out_size) {
    const float* input = (const float*)d_in[0];
    const float* target = (const float*)d_in[1];
    float* out = (float*)d_out;

    cudaFuncSetAttribute(ssim_kernel, cudaFuncAttributeMaxDynamicSharedMemorySize, SMEM_BYTES);

    zero_out_kernel<<<1, 1>>>(out);
    dim3 grid(IMG / TW, IMG / TH, NPLANES);
    ssim_kernel<<<grid, 256, SMEM_BYTES>>>(input, target, out);
}

// round 10
// speedup vs baseline: 1.1189x; 1.1189x over previous
#include <cuda_runtime.h>

// SSIM loss: depthwise 11x11 gaussian (separable) + pointwise SSIM + global mean.
// B=16, C=3, H=W=512. Planes = 48. Tile 32x32 per block, halo 5 each side.
//
// Round 10: fused-pair phase 2 (single row read -> both blur pairs, from R9)
// + 128-thread register-resident phase 3 (from R7, no smem exchange)
// + __launch_bounds__(256,5) so neither phase spills (51-reg budget).
// R9's occ-6 cap caused spills (L2 35%); this keeps the wf win without them.

typedef unsigned long long u64;

#define TW 32
#define TH 32
#define HALO 5
#define SH 42
#define SW 42
#define IMG 512
#define NPLANES 48

#define RS 90            // (t,i) pair-plane row stride (floats): LDS.64 conflict-free
#define PP 3780          // SH * RS
#define CS 84            // sHT column stride (floats): quad 5*tx mod 8 distinct -> LDS.128 conflict-free
#define PT 2688          // 32 * CS, per-pair sHT plane

#define OFF_HT PP
#define OFF_RED (OFF_HT + 2 * PT)
#define SMEM_FLOATS (OFF_RED + 8)
#define SMEM_BYTES (SMEM_FLOATS * 4)   // 36656 B

__device__ constexpr float GW[11] = {
    0.00102838f, 0.00759877f, 0.03600077f, 0.10936079f, 0.21300554f,
    0.26601173f,
    0.21300554f, 0.10936079f, 0.03600077f, 0.00759877f, 0.00102838f};

#define SSIM_C1 0.0001f
#define SSIM_C2 0.0009f
#define INV_N (1.0f / (16.0f * 3.0f * 512.0f * 512.0f))

__device__ __forceinline__ u64 pack2(float lo, float hi) {
    u64 r;
    asm("mov.b64 %0, {%1, %2};" : "=l"(r) : "f"(lo), "f"(hi));
    return r;
}
__device__ __forceinline__ void unpack2(u64 v, float& lo, float& hi) {
    asm("mov.b64 {%0, %1}, %2;" : "=f"(lo), "=f"(hi) : "l"(v));
}
__device__ __forceinline__ u64 ffma2(u64 a, u64 b, u64 c) {
    u64 d;
    asm("fma.rn.f32x2 %0, %1, %2, %3;" : "=l"(d) : "l"(a), "l"(b), "l"(c));
    return d;
}
__device__ __forceinline__ u64 bcast2(float g) {
    unsigned u = __float_as_uint(g);
    return ((u64)u << 32) | (u64)u;
}

// Streaming vertical blur: 8 outputs from 18 consecutive row values of one column.
__device__ __forceinline__ void v_blur8(const float* __restrict__ base, u64 (&acc)[8]) {
#pragma unroll
    for (int r = 0; r < 8; r++) acc[r] = 0ull;
#pragma unroll
    for (int q = 0; q < 9; q++) {
        ulonglong2 vv = *(const ulonglong2*)(base + q * 4);
#pragma unroll
        for (int e = 0; e < 2; e++) {
            const int j = 2 * q + e;
            u64 v = e ? vv.y : vv.x;
#pragma unroll
            for (int r = 0; r < 8; r++) {
                if (j - r >= 0 && j - r < 11) acc[r] = ffma2(v, bcast2(GW[j - r]), acc[r]);
            }
        }
    }
}

__global__ void zero_out_kernel(float* out) { out[0] = 0.0f; }

__global__ __launch_bounds__(256, 5)
void ssim_kernel(const float* __restrict__ input, const float* __restrict__ target,
                 float* __restrict__ out) {
    extern __shared__ float smem[];
    float* sHT = smem + OFF_HT;
    float* red = smem + OFF_RED;

    const int tid = threadIdx.x;
    const int plane = blockIdx.z;
    const float* Tp = target + (size_t)plane * (IMG * IMG);
    const float* Ip = input + (size_t)plane * (IMG * IMG);
    const int gx0 = blockIdx.x * TW - HALO;
    const int gy0 = blockIdx.y * TH - HALO;

    // ---- Phase 1: load tile (+halo), store interleaved (t,i) pairs ----
    for (int idx = tid; idx < SH * SW; idx += 256) {
        int r = idx / SW;
        int c = idx - r * SW;
        int gx = gx0 + c;
        int gy = gy0 + r;
        float t = 0.0f, v = 0.0f;
        if ((unsigned)gx < (unsigned)IMG && (unsigned)gy < (unsigned)IMG) {
            t = Tp[gy * IMG + gx];
            v = Ip[gy * IMG + gx];
        }
        *(u64*)(smem + r * RS + c * 2) = pack2(t, v);
    }
    __syncthreads();

    // ---- Phase 2: fused-pair horizontal blur.
    // Task = (row, 8-col chunk). Warps 0-3: chunk = w, row = lane (0..31).
    // Warps 4-7: idx = (w-4)*32+lane < 40 -> chunk = idx/10, row = 32 + idx%10.
    {
        const int w = tid >> 5;
        const int lane = tid & 31;
        int row, c0;
        bool active = true;
        if (w < 4) {
            c0 = w * 8;
            row = lane;
        } else {
            int idx = (w - 4) * 32 + lane;
            active = (idx < 40);
            int chunk = idx / 10;
            row = 32 + idx - chunk * 10;
            c0 = chunk * 8;
        }
        if (active) {
            const float* rowBase = smem + row * RS + c0 * 2;
            u64 a0[8], a1[8];
#pragma unroll
            for (int r = 0; r < 8; r++) { a0[r] = 0ull; a1[r] = 0ull; }
#pragma unroll
            for (int j = 0; j < 18; j++) {
                u64 v = *(const u64*)(rowBase + j * 2);
                float t, i;
                unpack2(v, t, i);
                u64 p = pack2(fmaf(t, t, i * i), t * i);
#pragma unroll
                for (int r = 0; r < 8; r++) {
                    if (j - r >= 0 && j - r < 11) {
                        a0[r] = ffma2(v, bcast2(GW[j - r]), a0[r]);
                        a1[r] = ffma2(p, bcast2(GW[j - r]), a1[r]);
                    }
                }
            }
            float* d0 = sHT + c0 * CS + row * 2;
            float* d1 = d0 + PT;
#pragma unroll
            for (int r = 0; r < 8; r++) {
                *(u64*)(d0 + r * CS) = a0[r];
                *(u64*)(d1 + r * CS) = a1[r];
            }
        }
    }
    __syncthreads();

    // ---- Phase 3: vertical blur + SSIM. 128 threads: (tx = col, tg = 8-row group).
    float acc = 0.0f;
    if (tid < 128) {
        const int tx = tid & 31;
        const int tg = tid >> 5;  // 0..3, output rows [8*tg, 8*tg+8)

        u64 mu[8];
        v_blur8(sHT + tx * CS + tg * 16, mu);        // pair 0 -> (mu1, mu2)
        u64 pr[8];
        v_blur8(sHT + PT + tx * CS + tg * 16, pr);   // pair 1 -> (Eq, E12)

#pragma unroll
        for (int r = 0; r < 8; r++) {
            float mu1, mu2, eq, e12;
            unpack2(mu[r], mu1, mu2);
            unpack2(pr[r], eq, e12);
            float mu1s = mu1 * mu1;
            float mu2s = mu2 * mu2;
            float mu12 = mu1 * mu2;
            float musum = mu1s + mu2s;
            float ssum = eq - musum;   // sigma1^2 + sigma2^2
            float s12 = e12 - mu12;
            float num = (2.0f * mu12 + SSIM_C1) * (2.0f * s12 + SSIM_C2);
            float den = (musum + SSIM_C1) * (ssum + SSIM_C2);
            float ssim = __fdividef(num, den);
            // mask: conflict-free LDS.64 of the (t,i) pair; use t lane
            u64 tv = *(const u64*)(smem + (HALO + tg * 8 + r) * RS + (HALO + tx) * 2);
            float tc, ic;
            unpack2(tv, tc, ic);
            acc += (tc > 0.0f) ? (1.0f - ssim) : 0.0f;
        }

#pragma unroll
        for (int off = 16; off; off >>= 1) acc += __shfl_xor_sync(0xFFFFFFFFu, acc, off);
        if (tx == 0) red[tg] = acc;
    }
    __syncthreads();
    if (tid == 0) {
        float s = red[0] + red[1] + red[2] + red[3];
        atomicAdd(out, s * INV_N);
    }
}

extern "C" void kernel_launch(void* const* d_in, const int* in_sizes, int n_in,
                              void* d_out, int out_size) {
    const float* input = (const float*)d_in[0];
    const float* target = (const float*)d_in[1];
    float* out = (float*)d_out;

    cudaFuncSetAttribute(ssim_kernel, cudaFuncAttributeMaxDynamicSharedMemorySize, SMEM_BYTES);

    zero_out_kernel<<<1, 1>>>(out);
    dim3 grid(IMG / TW, IMG / TH, NPLANES);
    ssim_kernel<<<grid, 256, SMEM_BYTES>>>(input, target, out);
}

// round 11
// speedup vs baseline: 1.1777x; 1.0525x over previous
#include <cuda_runtime.h>

// SSIM loss: depthwise 11x11 gaussian (separable) + pointwise SSIM + global mean.
// B=16, C=3, H=W=512. Planes = 48. Tile 32x32 per block, halo 5 each side.
//
// Round 11: occ-6 config (best, from R8) with the smem pair-exchange replaced by
// an in-warp shuffle exchange. P3 warp = (16 cols, one 8-row group, BOTH pairs):
// lanes 0-15 blur pair 0, lanes 16-31 pair 1; 4x shfl.xor(16) of u64 swaps the
// needed half of results; SSIM rows split between half-warps. No exchange smem,
// no extra barriers, ~30 live regs in P3 -> no spills at the 42-reg occ-6 cap.

typedef unsigned long long u64;

#define TW 32
#define TH 32
#define HALO 5
#define SH 42
#define SW 42
#define IMG 512
#define NPLANES 48

#define RS 90            // (t,i) pair-plane row stride (floats): LDS.64 conflict-free
#define PP 3780          // SH * RS
#define CS 84            // sHT column stride (floats): quad 5*col mod 8 distinct -> LDS.128 conflict-free
#define PT 2688          // 32 * CS, per-pair sHT plane

#define OFF_HT PP
#define OFF_RED (OFF_HT + 2 * PT)
#define SMEM_FLOATS (OFF_RED + 8)
#define SMEM_BYTES (SMEM_FLOATS * 4)   // 36656 B -> 6 blocks/SM

__device__ constexpr float GW[11] = {
    0.00102838f, 0.00759877f, 0.03600077f, 0.10936079f, 0.21300554f,
    0.26601173f,
    0.21300554f, 0.10936079f, 0.03600077f, 0.00759877f, 0.00102838f};

#define SSIM_C1 0.0001f
#define SSIM_C2 0.0009f
#define INV_N (1.0f / (16.0f * 3.0f * 512.0f * 512.0f))

__device__ __forceinline__ u64 pack2(float lo, float hi) {
    u64 r;
    asm("mov.b64 %0, {%1, %2};" : "=l"(r) : "f"(lo), "f"(hi));
    return r;
}
__device__ __forceinline__ void unpack2(u64 v, float& lo, float& hi) {
    asm("mov.b64 {%0, %1}, %2;" : "=f"(lo), "=f"(hi) : "l"(v));
}
__device__ __forceinline__ u64 ffma2(u64 a, u64 b, u64 c) {
    u64 d;
    asm("fma.rn.f32x2 %0, %1, %2, %3;" : "=l"(d) : "l"(a), "l"(b), "l"(c));
    return d;
}
__device__ __forceinline__ u64 bcast2(float g) {
    unsigned u = __float_as_uint(g);
    return ((u64)u << 32) | (u64)u;
}

// Horizontal sliding blur of 11 output cols starting at c0 of one row.
template <bool IS_PROD>
__device__ __forceinline__ void h_blur_task(const float* __restrict__ rowBase,
                                            float* __restrict__ dstBase, int c0, int row) {
    u64 acc[11];
#pragma unroll
    for (int r = 0; r < 11; r++) acc[r] = 0ull;
#pragma unroll
    for (int j = 0; j < 21; j++) {
        u64 v;
        if (IS_PROD) {
            float2 ti = *(const float2*)(rowBase + (c0 + j) * 2);
            v = pack2(fmaf(ti.x, ti.x, ti.y * ti.y), ti.x * ti.y);
        } else {
            v = *(const u64*)(rowBase + (c0 + j) * 2);
        }
#pragma unroll
        for (int r = 0; r < 11; r++) {
            if (j - r >= 0 && j - r < 11) acc[r] = ffma2(v, bcast2(GW[j - r]), acc[r]);
        }
    }
#pragma unroll
    for (int r = 0; r < 11; r++) *(u64*)(dstBase + (c0 + r) * CS + row * 2) = acc[r];
}

// Streaming vertical blur: 8 outputs from 18 consecutive row values of one column.
__device__ __forceinline__ void v_blur8(const float* __restrict__ base, u64 (&acc)[8]) {
#pragma unroll
    for (int r = 0; r < 8; r++) acc[r] = 0ull;
#pragma unroll
    for (int q = 0; q < 9; q++) {
        ulonglong2 vv = *(const ulonglong2*)(base + q * 4);
#pragma unroll
        for (int e = 0; e < 2; e++) {
            const int j = 2 * q + e;
            u64 v = e ? vv.y : vv.x;
#pragma unroll
            for (int r = 0; r < 8; r++) {
                if (j - r >= 0 && j - r < 11) acc[r] = ffma2(v, bcast2(GW[j - r]), acc[r]);
            }
        }
    }
}

__global__ void zero_out_kernel(float* out) { out[0] = 0.0f; }

__global__ __launch_bounds__(256, 6)
void ssim_kernel(const float* __restrict__ input, const float* __restrict__ target,
                 float* __restrict__ out) {
    extern __shared__ float smem[];
    float* sHT = smem + OFF_HT;
    float* red = smem + OFF_RED;

    const int tid = threadIdx.x;
    const int plane = blockIdx.z;
    const float* Tp = target + (size_t)plane * (IMG * IMG);
    const float* Ip = input + (size_t)plane * (IMG * IMG);
    const int gx0 = blockIdx.x * TW - HALO;
    const int gy0 = blockIdx.y * TH - HALO;

    // ---- Phase 1: load tile (+halo), store interleaved (t,i) pairs ----
    for (int idx = tid; idx < SH * SW; idx += 256) {
        int r = idx / SW;
        int c = idx - r * SW;
        int gx = gx0 + c;
        int gy = gy0 + r;
        float t = 0.0f, v = 0.0f;
        if ((unsigned)gx < (unsigned)IMG && (unsigned)gy < (unsigned)IMG) {
            t = Tp[gy * IMG + gx];
            v = Ip[gy * IMG + gx];
        }
        *(u64*)(smem + r * RS + c * 2) = pack2(t, v);
    }
    __syncthreads();

    // ---- Phase 2: split-pair horizontal blur, warp-uniform tasks (R8 layout) ----
    {
        const int w = tid >> 5;
        const int lane = tid & 31;
        int pair, c0, row;
        bool active;
        if (w < 6) {
            pair = (w >= 3) ? 1 : 0;
            int cw = w - 3 * pair;
            c0 = (cw == 2) ? 21 : cw * 11;
            row = lane;
            active = true;
        } else {
            pair = w - 6;
            int seg = (lane >= 20) ? 2 : (lane >= 10 ? 1 : 0);
            c0 = (seg == 2) ? 21 : seg * 11;
            row = 32 + lane - seg * 10;
            active = (lane < 30);
        }
        if (active) {
            const float* rowBase = smem + row * RS;
            if (pair == 0)
                h_blur_task<false>(rowBase, sHT, c0, row);
            else
                h_blur_task<true>(rowBase, sHT + PT, c0, row);
        }
    }
    __syncthreads();

    // ---- Phase 3: vertical blur + shuffle exchange + SSIM.
    // Warp w: col group c = w&1 (cols 16c..16c+15), row group tg = w>>1.
    // Lanes 0-15: pair 0; lanes 16-31: pair 1; same columns.
    {
        const int w = tid >> 5;
        const int lane = tid & 31;
        const int tx = lane & 15;
        const int half = lane >> 4;       // 0 = pair 0, 1 = pair 1
        const int col = (w & 1) * 16 + tx;
        const int tg = w >> 1;            // output rows [8*tg, 8*tg+8)

        u64 res[8];
        v_blur8(sHT + half * PT + col * CS + tg * 16, res);

        float acc = 0.0f;
#pragma unroll
        for (int k = 0; k < 4; k++) {
            // half 0 handles rows k (needs partner's res[k] = pair-1 stats);
            // half 1 handles rows k+4 (needs partner's res[k+4] = pair-0 stats).
            u64 send = half ? res[k] : res[k + 4];
            u64 recv = __shfl_xor_sync(0xFFFFFFFFu, send, 16);
            u64 muv = half ? recv : res[k];        // (mu1, mu2)
            u64 prv = half ? res[k + 4] : recv;    // (Eq, E12)

            float mu1, mu2, eq, e12;
            unpack2(muv, mu1, mu2);
            unpack2(prv, eq, e12);
            float mu1s = mu1 * mu1;
            float mu2s = mu2 * mu2;
            float mu12 = mu1 * mu2;
            float musum = mu1s + mu2s;
            float ssum = eq - musum;   // sigma1^2 + sigma2^2
            float s12 = e12 - mu12;
            float num = (2.0f * mu12 + SSIM_C1) * (2.0f * s12 + SSIM_C2);
            float den = (musum + SSIM_C1) * (ssum + SSIM_C2);
            float ssim = __fdividef(num, den);

            int row = tg * 8 + k + half * 4;
            u64 tv = *(const u64*)(smem + (HALO + row) * RS + (HALO + col) * 2);
            float tc, ic;
            unpack2(tv, tc, ic);
            acc += (tc > 0.0f) ? (1.0f - ssim) : 0.0f;
        }

        // warp covers its full (16 cols x 8 rows) patch across both halves
#pragma unroll
        for (int off = 16; off; off >>= 1) acc += __shfl_xor_sync(0xFFFFFFFFu, acc, off);
        if (lane == 0) red[w] = acc;
    }
    __syncthreads();
    if (tid == 0) {
        float s = 0.0f;
#pragma unroll
        for (int w = 0; w < 8; w++) s += red[w];
        atomicAdd(out, s * INV_N);
    }
}

extern "C" void kernel_launch(void* const* d_in, const int* in_sizes, int n_in,
                              void* d_out, int out_size) {
    const float* input = (const float*)d_in[0];
    const float* target = (const float*)d_in[1];
    float* out = (float*)d_out;

    cudaFuncSetAttribute(ssim_kernel, cudaFuncAttributeMaxDynamicSharedMemorySize, SMEM_BYTES);

    zero_out_kernel<<<1, 1>>>(out);
    dim3 grid(IMG / TW, IMG / TH, NPLANES);
    ssim_kernel<<<grid, 256, SMEM_BYTES>>>(input, target, out);
}